// round 4
// baseline (speedup 1.0000x reference)
#include <cuda_runtime.h>
#include <math.h>

#define BB 8
#define VV 6890
#define FF 13776
#define NP 4096
#define EPSF 1e-12f
#define NC ((FF + 15) / 16)          // 861 coarse CDF entries
#define NFB ((BB * FF + 255) / 256)  // 431 k_faces blocks
#define RBLK 64                      // row blocks per batch (4096/64)

// ---------------- device scratch (no allocations allowed) ----------------
__device__ float        g_cdf[BB * FF];            // per-face area -> CDF
__device__ float4       g_fn [BB * FF];            // per-face unit normals
__device__ float4       g_pts[2 * BB * NP];        // sampled points, w=|p|^2
__device__ float4       g_nrm[2 * BB * NP];        // sampled normals
__device__ unsigned int g_rowm[BB * NP];           // per-row mangled min (bits)
__device__ float        g_colp[BB * RBLK * NP];    // col-min partials (8MB)
__device__ float        g_edge[NFB];               // edge-loss block partials
__device__ float        g_part[512];               // k_post block partials (d,n)

// ---------------- kernels ----------------

// Per (b,f): area, unit normal, edge partial per block.
__global__ void k_faces(const float* __restrict__ verts,
                        const int*   __restrict__ faces) {
    int id = blockIdx.x * blockDim.x + threadIdx.x;
    float esum = 0.f;
    if (id < BB * FF) {
        int b = id / FF, f = id % FF;
        int i0 = faces[f * 3 + 0];
        int i1 = faces[f * 3 + 1];
        int i2 = faces[f * 3 + 2];
        const float* vb = verts + (size_t)b * VV * 3;
        float ax = vb[i0*3+0], ay = vb[i0*3+1], az = vb[i0*3+2];
        float bx = vb[i1*3+0], by = vb[i1*3+1], bz = vb[i1*3+2];
        float cx = vb[i2*3+0], cy = vb[i2*3+1], cz = vb[i2*3+2];
        float ux = bx-ax, uy = by-ay, uz = bz-az;   // v1-v0
        float wx = cx-ax, wy = cy-ay, wz = cz-az;   // v2-v0
        float crx = uy*wz - uz*wy;
        float cry = uz*wx - ux*wz;
        float crz = ux*wy - uy*wx;
        float cn  = sqrtf(crx*crx + cry*cry + crz*crz);
        g_cdf[id] = 0.5f * cn;
        float inv = 1.f / (cn + EPSF);
        g_fn[id]  = make_float4(crx*inv, cry*inv, crz*inv, 0.f);
        float ex = bx-cx, ey = by-cy, ez = bz-cz;   // v1-v2
        esum = (ux*ux + uy*uy + uz*uz)
             + (ex*ex + ey*ey + ez*ez)
             + (wx*wx + wy*wy + wz*wz);
    }
    __shared__ float sred[256];
    sred[threadIdx.x] = esum;
    __syncthreads();
    for (int s = 128; s > 0; s >>= 1) {
        if (threadIdx.x < s) sred[threadIdx.x] += sred[threadIdx.x + s];
        __syncthreads();
    }
    if (threadIdx.x == 0) g_edge[blockIdx.x] = sred[0];
}

// Per-batch inclusive scan of areas -> normalized CDF. One block per batch.
__global__ void k_scan() {
    const int CH = (FF + 1023) / 1024;     // 14
    int b = blockIdx.x;
    int t = threadIdx.x;
    float* a = g_cdf + (size_t)b * FF;
    int beg = t * CH;
    int end = min(beg + CH, FF);
    float loc[CH];
    float s = 0.f;
    for (int i = beg; i < end; i++) { s += a[i]; loc[i - beg] = s; }
    __shared__ float ss[1024];
    ss[t] = s;
    __syncthreads();
    for (int off = 1; off < 1024; off <<= 1) {
        float v = (t >= off) ? ss[t - off] : 0.f;
        __syncthreads();
        ss[t] += v;
        __syncthreads();
    }
    float total = ss[1023];
    float excl  = ss[t] - s;
    float scale = 1.f / (total + EPSF);
    for (int i = beg; i < end; i++) a[i] = (excl + loc[i - beg]) * scale;
}

// Sample points. grid (16 chunks, 8 batches, 2 sets), block 256.
__global__ void k_sample(const float* __restrict__ verts,
                         const int*   __restrict__ faces,
                         const float* __restrict__ rp,
                         const float* __restrict__ rg) {
    int set = blockIdx.z;
    int b   = blockIdx.y;
    int n   = blockIdx.x * 256 + threadIdx.x;
    const float* cdf = g_cdf + (size_t)b * FF;
    __shared__ float sc[NC];
    for (int i = threadIdx.x; i < NC; i += 256)
        sc[i] = cdf[i * 16 + 15];
    __syncthreads();

    const float* rnd = (set ? rg : rp) + ((size_t)b * NP + n) * 3;
    float u = rnd[0], r1 = rnd[1], r2 = rnd[2];

    // coarse: first k with sc[k] >= u
    int lo = 0, hi = NC;
    while (lo < hi) {
        int m = (lo + hi) >> 1;
        if (sc[m] < u) lo = m + 1; else hi = m;
    }
    int idx;
    if (lo == NC) {
        idx = FF - 1;
    } else {
        int l = lo * 16, h = l + 16;
        while (l < h) {
            int m = (l + h) >> 1;
            if (cdf[m] < u) l = m + 1; else h = m;
        }
        idx = min(l, FF - 1);
    }
    int i0 = faces[idx*3+0], i1 = faces[idx*3+1], i2 = faces[idx*3+2];
    const float* vb = verts + (size_t)b * VV * 3;
    float su = sqrtf(r1);
    float w0 = 1.f - su;
    float w1 = su * (1.f - r2);
    float w2 = su * r2;
    float x = w0*vb[i0*3+0] + w1*vb[i1*3+0] + w2*vb[i2*3+0];
    float y = w0*vb[i0*3+1] + w1*vb[i1*3+1] + w2*vb[i2*3+1];
    float z = w0*vb[i0*3+2] + w1*vb[i1*3+2] + w2*vb[i2*3+2];
    int out = set * BB * NP + b * NP + n;
    g_pts[out] = make_float4(x, y, z, x*x + y*y + z*z);
    g_nrm[out] = g_fn[(size_t)b * FF + idx];
}

// Fused chamfer: one pass over d[b,:,:], updates row-min (mangled argmin)
// and col-min (exact value) simultaneously.
// grid (RBLK=64, BB), block 256: 64 rows x 4096 cols per block,
// thread: 4 rows (ty) x 8 cols (tx) per 128-col tile.
__global__ void __launch_bounds__(256) k_cham() {
    const int b   = blockIdx.y;
    const int rb  = blockIdx.x * 64;
    const int tid = threadIdx.x;
    const int tx  = tid >> 4;      // 0..15 col group
    const int ty  = tid & 15;      // 0..15 row group
    const float4* __restrict__ P = g_pts + (size_t)b * NP;
    const float4* __restrict__ Q = g_pts + BB * NP + (size_t)b * NP;

    __shared__ float4 sq[128];
    __shared__ unsigned int srow[64][17];

    float px2[4], py2[4], pz2[4], pw[4], rowb[4];
    #pragma unroll
    for (int i = 0; i < 4; i++) {
        float4 p = P[rb + ty * 4 + i];
        px2[i] = -2.f * p.x;
        py2[i] = -2.f * p.y;
        pz2[i] = -2.f * p.z;
        pw[i]  = p.w;
        rowb[i] = __int_as_float(0x7F800000);   // +inf
    }

    for (int ct = 0; ct < NP; ct += 128) {
        if (tid < 128) sq[tid] = Q[ct + tid];
        __syncthreads();
        float colb[8];
        #pragma unroll
        for (int jj = 0; jj < 8; jj++) colb[jj] = __int_as_float(0x7F800000);
        #pragma unroll
        for (int jj = 0; jj < 8; jj++) {
            float4 q = sq[tx * 8 + jj];
            unsigned int col = ct + tx * 8 + jj;
            #pragma unroll
            for (int i = 0; i < 4; i++) {
                float d = fmaf(px2[i], q.x,
                          fmaf(py2[i], q.y,
                          fmaf(pz2[i], q.z, q.w))) + pw[i];
                unsigned int m = (__float_as_uint(d) & 0xFFFFF000u) | col;
                rowb[i]  = fminf(rowb[i], __uint_as_float(m));
                colb[jj] = fminf(colb[jj], d);
            }
        }
        // reduce col mins across ty (16 consecutive lanes)
        #pragma unroll
        for (int jj = 0; jj < 8; jj++) {
            float v = colb[jj];
            v = fminf(v, __shfl_xor_sync(0xffffffffu, v, 8, 16));
            v = fminf(v, __shfl_xor_sync(0xffffffffu, v, 4, 16));
            v = fminf(v, __shfl_xor_sync(0xffffffffu, v, 2, 16));
            v = fminf(v, __shfl_xor_sync(0xffffffffu, v, 1, 16));
            colb[jj] = v;
        }
        if (ty == 0) {
            int base = ((b * RBLK + blockIdx.x) << 12) + ct + tx * 8;
            *(float4*)&g_colp[base]     = make_float4(colb[0], colb[1], colb[2], colb[3]);
            *(float4*)&g_colp[base + 4] = make_float4(colb[4], colb[5], colb[6], colb[7]);
        }
        __syncthreads();
    }

    // reduce row mins across tx, then plain store (block-exclusive rows)
    #pragma unroll
    for (int i = 0; i < 4; i++) srow[ty * 4 + i][tx] = __float_as_uint(rowb[i]);
    __syncthreads();
    if (tid < 64) {
        float best = __uint_as_float(srow[tid][0]);
        #pragma unroll
        for (int k = 1; k < 16; k++)
            best = fminf(best, __uint_as_float(srow[tid][k]));
        g_rowm[(size_t)b * NP + rb + tid] = __float_as_uint(best);
    }
}

// Decode row mins (recompute exact distance + normal loss from argmin),
// reduce col partials; per-block partial sums to g_part (no atomics).
__global__ void k_post() {
    int gid = blockIdx.x * 256 + threadIdx.x;   // 0..65535
    float sd = 0.f, sn = 0.f;
    if (gid < BB * NP) {                        // rows -> dist1 + normals
        int b = gid >> 12;
        unsigned int m = g_rowm[gid];
        int col = m & 0xFFF;
        int qi  = BB * NP + (b << 12) + col;
        float4 p = g_pts[gid];
        float4 q = g_pts[qi];
        sd = p.w + q.w - 2.f * (p.x*q.x + p.y*q.y + p.z*q.z);
        float4 pn = g_nrm[gid];
        float4 qn = g_nrm[qi];
        sn = 1.f - fabsf(pn.x*qn.x + pn.y*qn.y + pn.z*qn.z);
    } else {                                    // cols -> dist2
        int c = gid - BB * NP;
        int b = c >> 12, col = c & 4095;
        float best = __int_as_float(0x7F800000);
        #pragma unroll 8
        for (int k = 0; k < RBLK; k++)
            best = fminf(best, g_colp[((b * RBLK + k) << 12) + col]);
        sd = best;
    }
    __shared__ float rA[256];
    __shared__ float rB[256];
    rA[threadIdx.x] = sd;
    rB[threadIdx.x] = sn;
    __syncthreads();
    for (int s = 128; s > 0; s >>= 1) {
        if (threadIdx.x < s) {
            rA[threadIdx.x] += rA[threadIdx.x + s];
            rB[threadIdx.x] += rB[threadIdx.x + s];
        }
        __syncthreads();
    }
    if (threadIdx.x == 0) {
        g_part[blockIdx.x * 2 + 0] = rA[0];
        g_part[blockIdx.x * 2 + 1] = rB[0];
    }
}

// Final: sum 256 block partials + 431 edge partials, compose loss.
__global__ void k_final(float* out) {
    int t = threadIdx.x;   // 256 threads
    float sd = g_part[t * 2 + 0];
    float sn = g_part[t * 2 + 1];
    float se = (t < NFB ? g_edge[t] : 0.f) + (t + 256 < NFB ? g_edge[t + 256] : 0.f);
    __shared__ float rA[256], rB[256], rC[256];
    rA[t] = sd; rB[t] = sn; rC[t] = se;
    __syncthreads();
    for (int s = 128; s > 0; s >>= 1) {
        if (t < s) { rA[t] += rA[t+s]; rB[t] += rB[t+s]; rC[t] += rC[t+s]; }
        __syncthreads();
    }
    if (t == 0) {
        double invBN = 1.0 / (double)(BB * NP);
        double cham  = (double)rA[0] * invBN;
        double nrm   = (double)rB[0] * invBN;
        double edge  = (double)rC[0] / (3.0 * (double)(BB * FF));
        out[0] = (float)(1.0 * cham + 0.1 * nrm + 0.5 * edge);
    }
}

// ---------------- launch ----------------
extern "C" void kernel_launch(void* const* d_in, const int* in_sizes, int n_in,
                              void* d_out, int out_size) {
    const float* pv = (const float*)d_in[0];   // predicted_vertices (B,V,3)
    const int*   pf = (const int*)  d_in[1];   // predicted_faces (F,3)
    // d_in[2], d_in[3] (gt mesh) unused by the reference computation
    const float* rp = (const float*)d_in[4];   // rand_pred (B,N,3)
    const float* rg = (const float*)d_in[5];   // rand_gt   (B,N,3)

    k_faces<<<NFB, 256>>>(pv, pf);
    k_scan<<<BB, 1024>>>();
    k_sample<<<dim3(16, BB, 2), 256>>>(pv, pf, rp, rg);
    k_cham<<<dim3(RBLK, BB), 256>>>();
    k_post<<<2 * BB * NP / 256, 256>>>();
    k_final<<<1, 256>>>((float*)d_out);
}

// round 5
// speedup vs baseline: 1.1343x; 1.1343x over previous
#include <cuda_runtime.h>
#include <math.h>

#define BB 8
#define VV 6890
#define FF 13776
#define NP 4096
#define EPSF 1e-12f
#define NC4 (FF / 4)                 // 3444 coarse CDF entries (stride 4)
#define NFB ((BB * FF + 255) / 256)  // 431 k_faces blocks
#define RBLK 128                     // row blocks per batch (4096/32)

// ---------------- device scratch (no allocations allowed) ----------------
__device__ float        g_cdf[BB * FF];            // per-face area -> CDF
__device__ float4       g_fn [BB * FF];            // per-face unit normals
__device__ float4       g_pts[2 * BB * NP];        // sampled points, w=|p|^2
__device__ float4       g_nrm[2 * BB * NP];        // sampled normals
__device__ unsigned int g_rowm[BB * NP];           // per-row mangled min (bits)
__device__ float        g_colp[BB * RBLK * NP];    // col-min partials (16.8MB)
__device__ float        g_edge[NFB];               // edge-loss block partials
__device__ float        g_part[512];               // k_post block partials (d,n)

// ---------------- packed f32x2 helpers ----------------
__device__ __forceinline__ unsigned long long pk2(float lo, float hi) {
    unsigned long long r;
    asm("mov.b64 %0, {%1, %2};" : "=l"(r) : "f"(lo), "f"(hi));
    return r;
}
__device__ __forceinline__ unsigned long long fma2(unsigned long long a,
                                                   unsigned long long b,
                                                   unsigned long long c) {
    unsigned long long d;
    asm("fma.rn.f32x2 %0, %1, %2, %3;" : "=l"(d) : "l"(a), "l"(b), "l"(c));
    return d;
}
__device__ __forceinline__ unsigned long long add2(unsigned long long a,
                                                   unsigned long long b) {
    unsigned long long d;
    asm("add.rn.f32x2 %0, %1, %2;" : "=l"(d) : "l"(a), "l"(b));
    return d;
}

// ---------------- kernels ----------------

// Per (b,f): area, unit normal, edge partial per block.
__global__ void k_faces(const float* __restrict__ verts,
                        const int*   __restrict__ faces) {
    int id = blockIdx.x * blockDim.x + threadIdx.x;
    float esum = 0.f;
    if (id < BB * FF) {
        int b = id / FF, f = id % FF;
        int i0 = faces[f * 3 + 0];
        int i1 = faces[f * 3 + 1];
        int i2 = faces[f * 3 + 2];
        const float* vb = verts + (size_t)b * VV * 3;
        float ax = vb[i0*3+0], ay = vb[i0*3+1], az = vb[i0*3+2];
        float bx = vb[i1*3+0], by = vb[i1*3+1], bz = vb[i1*3+2];
        float cx = vb[i2*3+0], cy = vb[i2*3+1], cz = vb[i2*3+2];
        float ux = bx-ax, uy = by-ay, uz = bz-az;   // v1-v0
        float wx = cx-ax, wy = cy-ay, wz = cz-az;   // v2-v0
        float crx = uy*wz - uz*wy;
        float cry = uz*wx - ux*wz;
        float crz = ux*wy - uy*wx;
        float cn  = sqrtf(crx*crx + cry*cry + crz*crz);
        g_cdf[id] = 0.5f * cn;
        float inv = 1.f / (cn + EPSF);
        g_fn[id]  = make_float4(crx*inv, cry*inv, crz*inv, 0.f);
        float ex = bx-cx, ey = by-cy, ez = bz-cz;   // v1-v2
        esum = (ux*ux + uy*uy + uz*uz)
             + (ex*ex + ey*ey + ez*ez)
             + (wx*wx + wy*wy + wz*wz);
    }
    __shared__ float sred[256];
    sred[threadIdx.x] = esum;
    __syncthreads();
    for (int s = 128; s > 0; s >>= 1) {
        if (threadIdx.x < s) sred[threadIdx.x] += sred[threadIdx.x + s];
        __syncthreads();
    }
    if (threadIdx.x == 0) g_edge[blockIdx.x] = sred[0];
}

// Per-batch inclusive scan of areas -> normalized CDF. One block per batch.
__global__ void k_scan() {
    const int CH = (FF + 1023) / 1024;     // 14
    int b = blockIdx.x;
    int t = threadIdx.x;
    float* a = g_cdf + (size_t)b * FF;
    int beg = t * CH;
    int end = min(beg + CH, FF);
    float loc[CH];
    float s = 0.f;
    for (int i = beg; i < end; i++) { s += a[i]; loc[i - beg] = s; }
    __shared__ float ss[1024];
    ss[t] = s;
    __syncthreads();
    for (int off = 1; off < 1024; off <<= 1) {
        float v = (t >= off) ? ss[t - off] : 0.f;
        __syncthreads();
        ss[t] += v;
        __syncthreads();
    }
    float total = ss[1023];
    float excl  = ss[t] - s;
    float scale = 1.f / (total + EPSF);
    for (int i = beg; i < end; i++) a[i] = (excl + loc[i - beg]) * scale;
}

// Sample points. grid (16 chunks, 8 batches, 2 sets), block 256.
// Coarse stride-4 CDF in shared (12 shared levels), then ONE float4 global
// probe resolves the final index: first j in [4k,4k+3] with cdf[j] >= u.
__global__ void k_sample(const float* __restrict__ verts,
                         const int*   __restrict__ faces,
                         const float* __restrict__ rp,
                         const float* __restrict__ rg) {
    int set = blockIdx.z;
    int b   = blockIdx.y;
    int n   = blockIdx.x * 256 + threadIdx.x;
    const float* cdf = g_cdf + (size_t)b * FF;
    __shared__ float sc[NC4];
    for (int i = threadIdx.x; i < NC4; i += 256)
        sc[i] = cdf[i * 4 + 3];
    __syncthreads();

    const float* rnd = (set ? rg : rp) + ((size_t)b * NP + n) * 3;
    float u = rnd[0], r1 = rnd[1], r2 = rnd[2];

    // coarse: first k with sc[k] >= u
    int lo = 0, hi = NC4;
    while (lo < hi) {
        int m = (lo + hi) >> 1;
        if (sc[m] < u) lo = m + 1; else hi = m;
    }
    int idx;
    if (lo == NC4) {
        idx = FF - 1;                       // u beyond cdf end -> clip
    } else {
        float4 seg = *(const float4*)&cdf[lo * 4];   // aligned (16B)
        idx = lo * 4 + (seg.x < u) + (seg.y < u) + (seg.z < u);
    }
    int i0 = faces[idx*3+0], i1 = faces[idx*3+1], i2 = faces[idx*3+2];
    const float* vb = verts + (size_t)b * VV * 3;
    float su = sqrtf(r1);
    float w0 = 1.f - su;
    float w1 = su * (1.f - r2);
    float w2 = su * r2;
    float x = w0*vb[i0*3+0] + w1*vb[i1*3+0] + w2*vb[i2*3+0];
    float y = w0*vb[i0*3+1] + w1*vb[i1*3+1] + w2*vb[i2*3+1];
    float z = w0*vb[i0*3+2] + w1*vb[i1*3+2] + w2*vb[i2*3+2];
    int out = set * BB * NP + b * NP + n;
    g_pts[out] = make_float4(x, y, z, x*x + y*y + z*z);
    g_nrm[out] = g_fn[(size_t)b * FF + idx];
}

// Fused chamfer, packed f32x2: one pass over d[b,:,:], row-min (mangled
// argmin) + col-min (exact value) together.
// grid (RBLK=128, BB), block 256: 32 rows x 4096 cols per block.
// Thread layout: ty = tid&7 (8 row groups x 4 rows), tx = tid>>3 (32 col
// groups x 4 cols per 128-col tile). Threads sharing columns are 8
// consecutive lanes -> cheap 8-lane shuffle reduce for col mins.
__global__ void __launch_bounds__(256) k_cham() {
    const int b   = blockIdx.y;
    const int rb  = blockIdx.x * 32;
    const int tid = threadIdx.x;
    const int tx  = tid >> 3;      // 0..31 col group
    const int ty  = tid & 7;       // 0..7 row group
    const float4* __restrict__ P = g_pts + (size_t)b * NP;
    const float4* __restrict__ Q = g_pts + BB * NP + (size_t)b * NP;

    __shared__ __align__(16) float sqx[128];
    __shared__ __align__(16) float sqy[128];
    __shared__ __align__(16) float sqz[128];
    __shared__ __align__(16) float sqw[128];
    __shared__ unsigned int srow[32][33];

    unsigned long long px2d[4], py2d[4], pz2d[4], pwd[4];
    float rowb[4];
    #pragma unroll
    for (int i = 0; i < 4; i++) {
        float4 p = P[rb + ty * 4 + i];
        float vx = -2.f * p.x, vy = -2.f * p.y, vz = -2.f * p.z;
        px2d[i] = pk2(vx, vx);
        py2d[i] = pk2(vy, vy);
        pz2d[i] = pk2(vz, vz);
        pwd[i]  = pk2(p.w, p.w);
        rowb[i] = __int_as_float(0x7F800000);   // +inf
    }

    for (int ct = 0; ct < NP; ct += 128) {
        if (tid < 128) {
            float4 q = Q[ct + tid];
            sqx[tid] = q.x; sqy[tid] = q.y; sqz[tid] = q.z; sqw[tid] = q.w;
        }
        __syncthreads();
        float colb[4];
        #pragma unroll
        for (int k = 0; k < 4; k++) colb[k] = __int_as_float(0x7F800000);

        #pragma unroll
        for (int jj = 0; jj < 2; jj++) {
            int c = tx * 4 + jj * 2;
            unsigned long long qx2 = *(const unsigned long long*)&sqx[c];
            unsigned long long qy2 = *(const unsigned long long*)&sqy[c];
            unsigned long long qz2 = *(const unsigned long long*)&sqz[c];
            unsigned long long qw2 = *(const unsigned long long*)&sqw[c];
            unsigned int col0 = ct + c;
            #pragma unroll
            for (int i = 0; i < 4; i++) {
                unsigned long long d2 =
                    add2(fma2(px2d[i], qx2,
                         fma2(py2d[i], qy2,
                         fma2(pz2d[i], qz2, qw2))), pwd[i]);
                unsigned int dlo = (unsigned int)d2;
                unsigned int dhi = (unsigned int)(d2 >> 32);
                float m0 = __uint_as_float((dlo & 0xFFFFF000u) | col0);
                float m1 = __uint_as_float((dhi & 0xFFFFF000u) | (col0 + 1));
                rowb[i] = fminf(rowb[i], fminf(m0, m1));
                colb[jj*2]   = fminf(colb[jj*2],   __uint_as_float(dlo));
                colb[jj*2+1] = fminf(colb[jj*2+1], __uint_as_float(dhi));
            }
        }
        // reduce col mins across the 8 ty lanes (consecutive, 8-lane groups)
        #pragma unroll
        for (int k = 0; k < 4; k++) {
            float v = colb[k];
            v = fminf(v, __shfl_xor_sync(0xffffffffu, v, 4, 8));
            v = fminf(v, __shfl_xor_sync(0xffffffffu, v, 2, 8));
            v = fminf(v, __shfl_xor_sync(0xffffffffu, v, 1, 8));
            colb[k] = v;
        }
        if (ty == 0) {
            int base = ((b * RBLK + blockIdx.x) << 12) + ct + tx * 4;
            *(float4*)&g_colp[base] = make_float4(colb[0], colb[1], colb[2], colb[3]);
        }
        __syncthreads();
    }

    // reduce row mins across the 32 tx groups, plain store (block-exclusive rows)
    #pragma unroll
    for (int i = 0; i < 4; i++) srow[ty * 4 + i][tx] = __float_as_uint(rowb[i]);
    __syncthreads();
    if (tid < 32) {
        float best = __uint_as_float(srow[tid][0]);
        #pragma unroll
        for (int k = 1; k < 32; k++)
            best = fminf(best, __uint_as_float(srow[tid][k]));
        g_rowm[(size_t)b * NP + rb + tid] = __float_as_uint(best);
    }
}

// Decode row mins (recompute exact distance + normal loss from argmin),
// reduce col partials; per-block partial sums to g_part (no atomics).
__global__ void k_post() {
    int gid = blockIdx.x * 256 + threadIdx.x;   // 0..65535
    float sd = 0.f, sn = 0.f;
    if (gid < BB * NP) {                        // rows -> dist1 + normals
        int b = gid >> 12;
        unsigned int m = g_rowm[gid];
        int col = m & 0xFFF;
        int qi  = BB * NP + (b << 12) + col;
        float4 p = g_pts[gid];
        float4 q = g_pts[qi];
        sd = p.w + q.w - 2.f * (p.x*q.x + p.y*q.y + p.z*q.z);
        float4 pn = g_nrm[gid];
        float4 qn = g_nrm[qi];
        sn = 1.f - fabsf(pn.x*qn.x + pn.y*qn.y + pn.z*qn.z);
    } else {                                    // cols -> dist2
        int c = gid - BB * NP;
        int b = c >> 12, col = c & 4095;
        float best = __int_as_float(0x7F800000);
        #pragma unroll 8
        for (int k = 0; k < RBLK; k++)
            best = fminf(best, g_colp[((b * RBLK + k) << 12) + col]);
        sd = best;
    }
    __shared__ float rA[256];
    __shared__ float rB[256];
    rA[threadIdx.x] = sd;
    rB[threadIdx.x] = sn;
    __syncthreads();
    for (int s = 128; s > 0; s >>= 1) {
        if (threadIdx.x < s) {
            rA[threadIdx.x] += rA[threadIdx.x + s];
            rB[threadIdx.x] += rB[threadIdx.x + s];
        }
        __syncthreads();
    }
    if (threadIdx.x == 0) {
        g_part[blockIdx.x * 2 + 0] = rA[0];
        g_part[blockIdx.x * 2 + 1] = rB[0];
    }
}

// Final: sum 256 block partials + 431 edge partials, compose loss.
__global__ void k_final(float* out) {
    int t = threadIdx.x;   // 256 threads
    float sd = g_part[t * 2 + 0];
    float sn = g_part[t * 2 + 1];
    float se = (t < NFB ? g_edge[t] : 0.f) + (t + 256 < NFB ? g_edge[t + 256] : 0.f);
    __shared__ float rA[256], rB[256], rC[256];
    rA[t] = sd; rB[t] = sn; rC[t] = se;
    __syncthreads();
    for (int s = 128; s > 0; s >>= 1) {
        if (t < s) { rA[t] += rA[t+s]; rB[t] += rB[t+s]; rC[t] += rC[t+s]; }
        __syncthreads();
    }
    if (t == 0) {
        double invBN = 1.0 / (double)(BB * NP);
        double cham  = (double)rA[0] * invBN;
        double nrm   = (double)rB[0] * invBN;
        double edge  = (double)rC[0] / (3.0 * (double)(BB * FF));
        out[0] = (float)(1.0 * cham + 0.1 * nrm + 0.5 * edge);
    }
}

// ---------------- launch ----------------
extern "C" void kernel_launch(void* const* d_in, const int* in_sizes, int n_in,
                              void* d_out, int out_size) {
    const float* pv = (const float*)d_in[0];   // predicted_vertices (B,V,3)
    const int*   pf = (const int*)  d_in[1];   // predicted_faces (F,3)
    // d_in[2], d_in[3] (gt mesh) unused by the reference computation
    const float* rp = (const float*)d_in[4];   // rand_pred (B,N,3)
    const float* rg = (const float*)d_in[5];   // rand_gt   (B,N,3)

    k_faces<<<NFB, 256>>>(pv, pf);
    k_scan<<<BB, 1024>>>();
    k_sample<<<dim3(16, BB, 2), 256>>>(pv, pf, rp, rg);
    k_cham<<<dim3(RBLK, BB), 256>>>();
    k_post<<<2 * BB * NP / 256, 256>>>();
    k_final<<<1, 256>>>((float*)d_out);
}